// round 1
// baseline (speedup 1.0000x reference)
#include <cuda_runtime.h>
#include <math.h>

#define N_NODES 100000
#define E_EDGES 800000
#define D 128
#define EPSV 1e-4f
#define LN_EPSV 1e-5f

// ---- scratch (device globals; no allocation allowed) ----
__device__ float g_h[(size_t)N_NODES * D];
__device__ float g_rate[(size_t)N_NODES * D];
__device__ float g_gamma[(size_t)N_NODES * D];
__device__ float g_agg[(size_t)N_NODES * D];
__device__ int   g_cnt[N_NODES];

// ---------------- zero agg + cnt ----------------
__global__ void k_zero() {
    int i = blockIdx.x * blockDim.x + threadIdx.x;
    const int total4 = N_NODES * D / 4;
    if (i < total4) ((float4*)g_agg)[i] = make_float4(0.f, 0.f, 0.f, 0.f);
    if (i < N_NODES) g_cnt[i] = 0;
}

// ---------------- count edges per destination row ----------------
__global__ void k_count(const int* __restrict__ row) {
    int e = blockIdx.x * blockDim.x + threadIdx.x;
    if (e < E_EDGES) atomicAdd(&g_cnt[row[e]], 1);
}

// ---------------- fused 3x GEMM: h / rate / gamma ----------------
// C[100000,128] = x @ W (+bias / softplus). blockIdx.y selects which matrix.
// Tile: 64 rows x 128 cols per block, 256 threads, each thread 8Mx4N via
// packed fma.rn.f32x2 (row-pairs packed in 64-bit regs).
#define XS_STRIDE 66   // padded, even (8B-aligned pair loads), reduces STS conflicts

__global__ __launch_bounds__(256) void k_gemm(
    const float* __restrict__ x,
    const float* __restrict__ W_fc, const float* __restrict__ b_fc,
    const float* __restrict__ W_rate,
    const float* __restrict__ W_rob, const float* __restrict__ b_rob)
{
    __shared__ float xs[32 * XS_STRIDE];  // [k][m] transposed tile
    __shared__ float ws[32 * 128];        // [k][j]

    const int tid = threadIdx.x;
    const int which = blockIdx.y;
    const float* W = (which == 0) ? W_fc : ((which == 1) ? W_rate : W_rob);
    const int m0 = blockIdx.x * 64;
    const int tx = tid & 31;   // col group (j = tx*4 + 0..3)
    const int ty = tid >> 5;   // row group (m = ty*8 + 0..7)

    unsigned long long acc2[4][4];  // [row-pair][col] packed f32x2 accumulators
    #pragma unroll
    for (int p = 0; p < 4; p++)
        #pragma unroll
        for (int j = 0; j < 4; j++) acc2[p][j] = 0ull;

    #pragma unroll 1
    for (int kc = 0; kc < 128; kc += 32) {
        // load x tile transposed: xs[k][m]
        #pragma unroll
        for (int q = tid; q < 512; q += 256) {
            int m = q >> 3;
            int kk = (q & 7) << 2;
            float4 v = make_float4(0.f, 0.f, 0.f, 0.f);
            if (m0 + m < N_NODES)
                v = *(const float4*)(x + (size_t)(m0 + m) * D + kc + kk);
            xs[(kk + 0) * XS_STRIDE + m] = v.x;
            xs[(kk + 1) * XS_STRIDE + m] = v.y;
            xs[(kk + 2) * XS_STRIDE + m] = v.z;
            xs[(kk + 3) * XS_STRIDE + m] = v.w;
        }
        // load W chunk: ws[k][j]
        #pragma unroll
        for (int q = tid; q < 1024; q += 256) {
            int k = q >> 5;
            int j = (q & 31) << 2;
            *(float4*)(ws + k * 128 + j) = *(const float4*)(W + (size_t)(kc + k) * D + j);
        }
        __syncthreads();

        #pragma unroll
        for (int k = 0; k < 32; k++) {
            unsigned long long a2[4];
            #pragma unroll
            for (int p = 0; p < 4; p++)
                a2[p] = *(const unsigned long long*)(xs + k * XS_STRIDE + ty * 8 + 2 * p);
            float4 bv = *(const float4*)(ws + k * 128 + tx * 4);
            unsigned long long b2[4];
            asm("mov.b64 %0, {%1,%1};" : "=l"(b2[0]) : "f"(bv.x));
            asm("mov.b64 %0, {%1,%1};" : "=l"(b2[1]) : "f"(bv.y));
            asm("mov.b64 %0, {%1,%1};" : "=l"(b2[2]) : "f"(bv.z));
            asm("mov.b64 %0, {%1,%1};" : "=l"(b2[3]) : "f"(bv.w));
            #pragma unroll
            for (int p = 0; p < 4; p++)
                #pragma unroll
                for (int j = 0; j < 4; j++)
                    asm("fma.rn.f32x2 %0, %1, %2, %0;" : "+l"(acc2[p][j]) : "l"(a2[p]), "l"(b2[j]));
        }
        __syncthreads();
    }

    // epilogue
    float bias[4] = {0.f, 0.f, 0.f, 0.f};
    if (which == 0) {
        float4 b = *(const float4*)(b_fc + tx * 4);
        bias[0] = b.x; bias[1] = b.y; bias[2] = b.z; bias[3] = b.w;
    } else if (which == 2) {
        float4 b = *(const float4*)(b_rob + tx * 4);
        bias[0] = b.x; bias[1] = b.y; bias[2] = b.z; bias[3] = b.w;
    }
    float* outp = (which == 0) ? g_h : ((which == 1) ? g_rate : g_gamma);

    #pragma unroll
    for (int p = 0; p < 4; p++) {
        float lo[4], hi[4];
        #pragma unroll
        for (int j = 0; j < 4; j++)
            asm("mov.b64 {%0,%1}, %2;" : "=f"(lo[j]), "=f"(hi[j]) : "l"(acc2[p][j]));
        int m_lo = m0 + ty * 8 + 2 * p;
        int m_hi = m_lo + 1;
        float4 vlo, vhi;
        float* plo = (float*)&vlo; float* phi = (float*)&vhi;
        #pragma unroll
        for (int j = 0; j < 4; j++) {
            float a = lo[j], b = hi[j];
            if (which == 1) {  // softplus + EPS (no bias)
                a = ((a > 20.f) ? a : log1pf(__expf(a))) + EPSV;
                b = ((b > 20.f) ? b : log1pf(__expf(b))) + EPSV;
            } else {
                a += bias[j]; b += bias[j];
            }
            plo[j] = a; phi[j] = b;
        }
        if (m_lo < N_NODES) *(float4*)(outp + (size_t)m_lo * D + tx * 4) = vlo;
        if (m_hi < N_NODES) *(float4*)(outp + (size_t)m_hi * D + tx * 4) = vhi;
    }
}

// ---------------- scatter: agg[row] += h[col]  (one warp per edge) ----------------
__global__ __launch_bounds__(256) void k_scatter(const int* __restrict__ row,
                                                 const int* __restrict__ col) {
    int w = (blockIdx.x * blockDim.x + threadIdx.x) >> 5;
    int lane = threadIdx.x & 31;
    if (w >= E_EDGES) return;
    int r = row[w];
    int c = col[w];
    float4 v = ((const float4*)(g_h + (size_t)c * D))[lane];
    float* dst = g_agg + (size_t)r * D + lane * 4;
    asm volatile("red.global.add.v4.f32 [%0], {%1,%2,%3,%4};"
                 :: "l"(dst), "f"(v.x), "f"(v.y), "f"(v.z), "f"(v.w)
                 : "memory");
}

// ---------------- final: combine + LayerNorm  (one warp per node row) ----------------
__global__ __launch_bounds__(256) void k_final(const int* __restrict__ degree,
                                               const float* __restrict__ ln_g,
                                               const float* __restrict__ ln_b,
                                               float* __restrict__ out)
{
    int w = (blockIdx.x * blockDim.x + threadIdx.x) >> 5;
    int lane = threadIdx.x & 31;
    if (w >= N_NODES) return;
    size_t base = (size_t)w * D;
    float4 h4 = ((const float4*)(g_h + base))[lane];
    float4 a4 = ((const float4*)(g_agg + base))[lane];
    float4 r4 = ((const float4*)(g_rate + base))[lane];
    float4 g4 = ((const float4*)(g_gamma + base))[lane];
    float cnt = (float)g_cnt[w];
    float deg = (float)degree[w];

    float y[4];
    {
        const float* hp = (const float*)&h4;
        const float* ap = (const float*)&a4;
        const float* rp = (const float*)&r4;
        const float* gp = (const float*)&g4;
        #pragma unroll
        for (int i = 0; i < 4; i++) {
            float agg_full = ap[i] + cnt * hp[i];
            y[i] = (rp[i] * agg_full + gp[i]) / (1.0f + rp[i] * deg + EPSV);
        }
    }

    float s = y[0] + y[1] + y[2] + y[3];
    float s2 = y[0]*y[0] + y[1]*y[1] + y[2]*y[2] + y[3]*y[3];
    #pragma unroll
    for (int off = 16; off > 0; off >>= 1) {
        s  += __shfl_xor_sync(0xffffffffu, s,  off);
        s2 += __shfl_xor_sync(0xffffffffu, s2, off);
    }
    float mean = s * (1.0f / D);
    float var = s2 * (1.0f / D) - mean * mean;
    float rstd = rsqrtf(var + LN_EPSV);

    float4 lg = ((const float4*)ln_g)[lane];
    float4 lb = ((const float4*)ln_b)[lane];
    float4 o;
    o.x = (y[0] - mean) * rstd * lg.x + lb.x;
    o.y = (y[1] - mean) * rstd * lg.y + lb.y;
    o.z = (y[2] - mean) * rstd * lg.z + lb.z;
    o.w = (y[3] - mean) * rstd * lg.w + lb.w;
    ((float4*)(out + base))[lane] = o;
}

// ---------------- launch ----------------
extern "C" void kernel_launch(void* const* d_in, const int* in_sizes, int n_in,
                              void* d_out, int out_size) {
    const float* x      = (const float*)d_in[0];
    const int*   ei     = (const int*)  d_in[1];
    const int*   degree = (const int*)  d_in[2];
    const float* W_fc   = (const float*)d_in[3];
    const float* b_fc   = (const float*)d_in[4];
    const float* W_rate = (const float*)d_in[5];
    const float* W_rob  = (const float*)d_in[6];
    const float* b_rob  = (const float*)d_in[7];
    const float* ln_g   = (const float*)d_in[8];
    const float* ln_b   = (const float*)d_in[9];
    float* out = (float*)d_out;

    const int* row = ei;             // edge_index[0]
    const int* col = ei + E_EDGES;   // edge_index[1]

    k_zero<<<(N_NODES * D / 4 + 255) / 256, 256>>>();
    k_count<<<(E_EDGES + 255) / 256, 256>>>(row);
    dim3 ggrid((N_NODES + 63) / 64, 3);
    k_gemm<<<ggrid, 256>>>(x, W_fc, b_fc, W_rate, W_rob, b_rob);
    k_scatter<<<(int)(((size_t)E_EDGES * 32 + 255) / 256), 256>>>(row, col);
    k_final<<<(int)(((size_t)N_NODES * 32 + 255) / 256), 256>>>(degree, ln_g, ln_b, out);
}

// round 2
// speedup vs baseline: 1.2053x; 1.2053x over previous
#include <cuda_runtime.h>
#include <math.h>

#define N_NODES 100000
#define E_EDGES 800000
#define D 128
#define EPSV 1e-4f
#define LN_EPSV 1e-5f

#define SCAN_B 512
#define NBLK ((N_NODES + SCAN_B - 1) / SCAN_B)   // 196

// ---- scratch (device globals; no allocation allowed) ----
__device__ float g_h[(size_t)N_NODES * D];
__device__ float g_rate[(size_t)N_NODES * D];
__device__ float g_gamma[(size_t)N_NODES * D];
__device__ int   g_cnt[N_NODES];
__device__ int   g_cur[N_NODES];
__device__ int   g_off[N_NODES];
__device__ int   g_bsum[NBLK];
__device__ int   g_ecol[E_EDGES];

// ---------------- zero cnt + cur ----------------
__global__ void k_zero() {
    int i = blockIdx.x * blockDim.x + threadIdx.x;
    if (i < N_NODES) { g_cnt[i] = 0; g_cur[i] = 0; }
}

// ---------------- count edges per destination row ----------------
__global__ void k_count(const int* __restrict__ row) {
    int e = blockIdx.x * blockDim.x + threadIdx.x;
    if (e < E_EDGES) atomicAdd(&g_cnt[row[e]], 1);
}

// ---------------- scan pass 1: block-local exclusive scan + block totals ----
__global__ __launch_bounds__(SCAN_B) void k_scan1() {
    __shared__ int wsum[SCAN_B / 32];
    int i = blockIdx.x * SCAN_B + threadIdx.x;
    int lane = threadIdx.x & 31;
    int wid = threadIdx.x >> 5;
    int v = (i < N_NODES) ? g_cnt[i] : 0;
    // inclusive warp scan
    int s = v;
    #pragma unroll
    for (int o = 1; o < 32; o <<= 1) {
        int t = __shfl_up_sync(0xffffffffu, s, o);
        if (lane >= o) s += t;
    }
    if (lane == 31) wsum[wid] = s;
    __syncthreads();
    if (wid == 0) {
        int ws = (lane < SCAN_B / 32) ? wsum[lane] : 0;
        #pragma unroll
        for (int o = 1; o < SCAN_B / 32; o <<= 1) {
            int t = __shfl_up_sync(0xffffffffu, ws, o);
            if (lane >= o) ws += t;
        }
        if (lane < SCAN_B / 32) wsum[lane] = ws;
    }
    __syncthreads();
    int base = (wid > 0) ? wsum[wid - 1] : 0;
    int excl = base + s - v;
    if (i < N_NODES) g_off[i] = excl;
    if (threadIdx.x == SCAN_B - 1) g_bsum[blockIdx.x] = base + s;
}

// ---------------- scan pass 2: exclusive scan of block totals (1 block) ----
__global__ __launch_bounds__(256) void k_scan2() {
    __shared__ int wsum[8];
    int lane = threadIdx.x & 31;
    int wid = threadIdx.x >> 5;
    int v = (threadIdx.x < NBLK) ? g_bsum[threadIdx.x] : 0;
    int s = v;
    #pragma unroll
    for (int o = 1; o < 32; o <<= 1) {
        int t = __shfl_up_sync(0xffffffffu, s, o);
        if (lane >= o) s += t;
    }
    if (lane == 31) wsum[wid] = s;
    __syncthreads();
    if (wid == 0) {
        int ws = (lane < 8) ? wsum[lane] : 0;
        #pragma unroll
        for (int o = 1; o < 8; o <<= 1) {
            int t = __shfl_up_sync(0xffffffffu, ws, o);
            if (lane >= o) ws += t;
        }
        if (lane < 8) wsum[lane] = ws;
    }
    __syncthreads();
    int base = (wid > 0) ? wsum[wid - 1] : 0;
    if (threadIdx.x < NBLK) g_bsum[threadIdx.x] = base + s - v;
}

// ---------------- scan pass 3: add block offsets ----------------
__global__ __launch_bounds__(SCAN_B) void k_scan3() {
    int i = blockIdx.x * SCAN_B + threadIdx.x;
    if (i < N_NODES) g_off[i] += g_bsum[blockIdx.x];
}

// ---------------- bin: place col indices into CSR edge array ----------------
__global__ __launch_bounds__(256) void k_bin(const int* __restrict__ row,
                                             const int* __restrict__ col) {
    int e = blockIdx.x * blockDim.x + threadIdx.x;
    if (e >= E_EDGES) return;
    int r = row[e];
    int pos = g_off[r] + atomicAdd(&g_cur[r], 1);
    g_ecol[pos] = col[e];
}

// ---------------- fused 3x GEMM: h / rate / gamma ----------------
#define XS_STRIDE 66

__global__ __launch_bounds__(256) void k_gemm(
    const float* __restrict__ x,
    const float* __restrict__ W_fc, const float* __restrict__ b_fc,
    const float* __restrict__ W_rate,
    const float* __restrict__ W_rob, const float* __restrict__ b_rob)
{
    __shared__ float xs[32 * XS_STRIDE];  // [k][m] transposed tile
    __shared__ float ws[32 * 128];        // [k][j]

    const int tid = threadIdx.x;
    const int which = blockIdx.y;
    const float* W = (which == 0) ? W_fc : ((which == 1) ? W_rate : W_rob);
    const int m0 = blockIdx.x * 64;
    const int tx = tid & 31;
    const int ty = tid >> 5;

    unsigned long long acc2[4][4];
    #pragma unroll
    for (int p = 0; p < 4; p++)
        #pragma unroll
        for (int j = 0; j < 4; j++) acc2[p][j] = 0ull;

    #pragma unroll 1
    for (int kc = 0; kc < 128; kc += 32) {
        #pragma unroll
        for (int q = tid; q < 512; q += 256) {
            int m = q >> 3;
            int kk = (q & 7) << 2;
            float4 v = make_float4(0.f, 0.f, 0.f, 0.f);
            if (m0 + m < N_NODES)
                v = *(const float4*)(x + (size_t)(m0 + m) * D + kc + kk);
            xs[(kk + 0) * XS_STRIDE + m] = v.x;
            xs[(kk + 1) * XS_STRIDE + m] = v.y;
            xs[(kk + 2) * XS_STRIDE + m] = v.z;
            xs[(kk + 3) * XS_STRIDE + m] = v.w;
        }
        #pragma unroll
        for (int q = tid; q < 1024; q += 256) {
            int k = q >> 5;
            int j = (q & 31) << 2;
            *(float4*)(ws + k * 128 + j) = *(const float4*)(W + (size_t)(kc + k) * D + j);
        }
        __syncthreads();

        #pragma unroll
        for (int k = 0; k < 32; k++) {
            unsigned long long a2[4];
            #pragma unroll
            for (int p = 0; p < 4; p++)
                a2[p] = *(const unsigned long long*)(xs + k * XS_STRIDE + ty * 8 + 2 * p);
            float4 bv = *(const float4*)(ws + k * 128 + tx * 4);
            unsigned long long b2[4];
            asm("mov.b64 %0, {%1,%1};" : "=l"(b2[0]) : "f"(bv.x));
            asm("mov.b64 %0, {%1,%1};" : "=l"(b2[1]) : "f"(bv.y));
            asm("mov.b64 %0, {%1,%1};" : "=l"(b2[2]) : "f"(bv.z));
            asm("mov.b64 %0, {%1,%1};" : "=l"(b2[3]) : "f"(bv.w));
            #pragma unroll
            for (int p = 0; p < 4; p++)
                #pragma unroll
                for (int j = 0; j < 4; j++)
                    asm("fma.rn.f32x2 %0, %1, %2, %0;" : "+l"(acc2[p][j]) : "l"(a2[p]), "l"(b2[j]));
        }
        __syncthreads();
    }

    float bias[4] = {0.f, 0.f, 0.f, 0.f};
    if (which == 0) {
        float4 b = *(const float4*)(b_fc + tx * 4);
        bias[0] = b.x; bias[1] = b.y; bias[2] = b.z; bias[3] = b.w;
    } else if (which == 2) {
        float4 b = *(const float4*)(b_rob + tx * 4);
        bias[0] = b.x; bias[1] = b.y; bias[2] = b.z; bias[3] = b.w;
    }
    float* outp = (which == 0) ? g_h : ((which == 1) ? g_rate : g_gamma);

    #pragma unroll
    for (int p = 0; p < 4; p++) {
        float lo[4], hi[4];
        #pragma unroll
        for (int j = 0; j < 4; j++)
            asm("mov.b64 {%0,%1}, %2;" : "=f"(lo[j]), "=f"(hi[j]) : "l"(acc2[p][j]));
        int m_lo = m0 + ty * 8 + 2 * p;
        int m_hi = m_lo + 1;
        float4 vlo, vhi;
        float* plo = (float*)&vlo; float* phi = (float*)&vhi;
        #pragma unroll
        for (int j = 0; j < 4; j++) {
            float a = lo[j], b = hi[j];
            if (which == 1) {
                a = ((a > 20.f) ? a : log1pf(__expf(a))) + EPSV;
                b = ((b > 20.f) ? b : log1pf(__expf(b))) + EPSV;
            } else {
                a += bias[j]; b += bias[j];
            }
            plo[j] = a; phi[j] = b;
        }
        if (m_lo < N_NODES) *(float4*)(outp + (size_t)m_lo * D + tx * 4) = vlo;
        if (m_hi < N_NODES) *(float4*)(outp + (size_t)m_hi * D + tx * 4) = vhi;
    }
}

// ---------------- fused gather + combine + LayerNorm (one warp per node) ----
__global__ __launch_bounds__(256) void k_final(const int* __restrict__ degree,
                                               const float* __restrict__ ln_g,
                                               const float* __restrict__ ln_b,
                                               float* __restrict__ out)
{
    int w = (blockIdx.x * blockDim.x + threadIdx.x) >> 5;
    int lane = threadIdx.x & 31;
    if (w >= N_NODES) return;
    size_t base = (size_t)w * D;

    int start = g_off[w];
    int cnt = g_cnt[w];

    // gather-sum of h[col] over this node's edges, 4-wide for MLP
    float4 acc = make_float4(0.f, 0.f, 0.f, 0.f);
    int j = 0;
    for (; j + 4 <= cnt; j += 4) {
        int c0 = g_ecol[start + j + 0];
        int c1 = g_ecol[start + j + 1];
        int c2 = g_ecol[start + j + 2];
        int c3 = g_ecol[start + j + 3];
        float4 v0 = ((const float4*)(g_h + (size_t)c0 * D))[lane];
        float4 v1 = ((const float4*)(g_h + (size_t)c1 * D))[lane];
        float4 v2 = ((const float4*)(g_h + (size_t)c2 * D))[lane];
        float4 v3 = ((const float4*)(g_h + (size_t)c3 * D))[lane];
        acc.x += (v0.x + v1.x) + (v2.x + v3.x);
        acc.y += (v0.y + v1.y) + (v2.y + v3.y);
        acc.z += (v0.z + v1.z) + (v2.z + v3.z);
        acc.w += (v0.w + v1.w) + (v2.w + v3.w);
    }
    for (; j < cnt; j++) {
        int c = g_ecol[start + j];
        float4 v = ((const float4*)(g_h + (size_t)c * D))[lane];
        acc.x += v.x; acc.y += v.y; acc.z += v.z; acc.w += v.w;
    }

    float4 h4 = ((const float4*)(g_h + base))[lane];
    float4 r4 = ((const float4*)(g_rate + base))[lane];
    float4 g4 = ((const float4*)(g_gamma + base))[lane];
    float fc = (float)cnt;
    float deg = (float)degree[w];

    float y[4];
    {
        const float* hp = (const float*)&h4;
        const float* ap = (const float*)&acc;
        const float* rp = (const float*)&r4;
        const float* gp = (const float*)&g4;
        float inv_den_common = 1.0f + EPSV;
        #pragma unroll
        for (int i = 0; i < 4; i++) {
            float agg_full = ap[i] + fc * hp[i];
            y[i] = (rp[i] * agg_full + gp[i]) / (inv_den_common + rp[i] * deg);
        }
    }

    float s = y[0] + y[1] + y[2] + y[3];
    float s2 = y[0]*y[0] + y[1]*y[1] + y[2]*y[2] + y[3]*y[3];
    #pragma unroll
    for (int off = 16; off > 0; off >>= 1) {
        s  += __shfl_xor_sync(0xffffffffu, s,  off);
        s2 += __shfl_xor_sync(0xffffffffu, s2, off);
    }
    float mean = s * (1.0f / D);
    float var = s2 * (1.0f / D) - mean * mean;
    float rstd = rsqrtf(var + LN_EPSV);

    float4 lg = ((const float4*)ln_g)[lane];
    float4 lb = ((const float4*)ln_b)[lane];
    float4 o;
    o.x = (y[0] - mean) * rstd * lg.x + lb.x;
    o.y = (y[1] - mean) * rstd * lg.y + lb.y;
    o.z = (y[2] - mean) * rstd * lg.z + lb.z;
    o.w = (y[3] - mean) * rstd * lg.w + lb.w;
    ((float4*)(out + base))[lane] = o;
}

// ---------------- launch ----------------
extern "C" void kernel_launch(void* const* d_in, const int* in_sizes, int n_in,
                              void* d_out, int out_size) {
    const float* x      = (const float*)d_in[0];
    const int*   ei     = (const int*)  d_in[1];
    const int*   degree = (const int*)  d_in[2];
    const float* W_fc   = (const float*)d_in[3];
    const float* b_fc   = (const float*)d_in[4];
    const float* W_rate = (const float*)d_in[5];
    const float* W_rob  = (const float*)d_in[6];
    const float* b_rob  = (const float*)d_in[7];
    const float* ln_g   = (const float*)d_in[8];
    const float* ln_b   = (const float*)d_in[9];
    float* out = (float*)d_out;

    const int* row = ei;             // edge_index[0]
    const int* col = ei + E_EDGES;   // edge_index[1]

    k_zero<<<(N_NODES + 255) / 256, 256>>>();
    k_count<<<(E_EDGES + 255) / 256, 256>>>(row);
    k_scan1<<<NBLK, SCAN_B>>>();
    k_scan2<<<1, 256>>>();
    k_scan3<<<NBLK, SCAN_B>>>();
    k_bin<<<(E_EDGES + 255) / 256, 256>>>(row, col);
    dim3 ggrid((N_NODES + 63) / 64, 3);
    k_gemm<<<ggrid, 256>>>(x, W_fc, b_fc, W_rate, W_rob, b_rob);
    k_final<<<(int)(((size_t)N_NODES * 32 + 255) / 256), 256>>>(degree, ln_g, ln_b, out);
}

// round 5
// speedup vs baseline: 1.4862x; 1.2330x over previous
#include <cuda_runtime.h>
#include <cuda_fp16.h>
#include <math.h>
#include <cstdint>

#define N_NODES 100000
#define E_EDGES 800000
#define D 128
#define EPSV 1e-4f
#define LN_EPSV 1e-5f

#define SCAN_B 512
#define NBLK ((N_NODES + SCAN_B - 1) / SCAN_B)   // 196

#define TILE_M 128
#define MM_CTAS ((N_NODES + TILE_M - 1) / TILE_M)  // 782

// ---- scratch (device globals; no allocation allowed) ----
__device__ float  g_h[(size_t)N_NODES * D];
__device__ float  g_rate[(size_t)N_NODES * D];
__device__ float  g_gamma[(size_t)N_NODES * D];
__device__ int    g_cnt[N_NODES];
__device__ int    g_cur[N_NODES];
__device__ int    g_off[N_NODES];
__device__ int    g_bsum[NBLK];
__device__ int    g_ecol[E_EDGES];
// fp16-split, transposed weights: [mat(3)][hi/lo(2)][n(128)][k(128)] halves
__device__ __half g_wh[3 * 2 * 128 * 128];

// ============================ helpers ============================
__device__ __forceinline__ uint32_t smem_u32(const void* p) {
    uint32_t a;
    asm("{ .reg .u64 t; cvta.to.shared.u64 t, %1; cvt.u32.u64 %0, t; }" : "=r"(a) : "l"(p));
    return a;
}

__device__ __forceinline__ void ldmatrix4(uint32_t* r, uint32_t addr) {
    asm volatile("ldmatrix.sync.aligned.m8n8.x4.shared.b16 {%0,%1,%2,%3}, [%4];"
                 : "=r"(r[0]), "=r"(r[1]), "=r"(r[2]), "=r"(r[3]) : "r"(addr));
}

__device__ __forceinline__ void mma16816(float* c, const uint32_t* a, uint32_t b0, uint32_t b1) {
    asm volatile("mma.sync.aligned.m16n8k16.row.col.f32.f16.f16.f32 "
                 "{%0,%1,%2,%3}, {%4,%5,%6,%7}, {%8,%9}, {%0,%1,%2,%3};"
                 : "+f"(c[0]), "+f"(c[1]), "+f"(c[2]), "+f"(c[3])
                 : "r"(a[0]), "r"(a[1]), "r"(a[2]), "r"(a[3]), "r"(b0), "r"(b1));
}

__device__ __forceinline__ void cp_async16(uint32_t saddr, const void* gaddr) {
    asm volatile("cp.async.cg.shared.global [%0], [%1], 16;" :: "r"(saddr), "l"(gaddr));
}
__device__ __forceinline__ void cp_commit() { asm volatile("cp.async.commit_group;"); }
__device__ __forceinline__ void cp_wait0()  { asm volatile("cp.async.wait_group 0;" ::: "memory"); }

// ============================ small kernels ============================
__global__ void k_zero() {
    int i = blockIdx.x * blockDim.x + threadIdx.x;
    if (i < N_NODES) { g_cnt[i] = 0; g_cur[i] = 0; }
}

__global__ void k_count(const int* __restrict__ row) {
    int e = blockIdx.x * blockDim.x + threadIdx.x;
    if (e < E_EDGES) atomicAdd(&g_cnt[row[e]], 1);
}

__global__ __launch_bounds__(SCAN_B) void k_scan1() {
    __shared__ int wsum[SCAN_B / 32];
    int i = blockIdx.x * SCAN_B + threadIdx.x;
    int lane = threadIdx.x & 31, wid = threadIdx.x >> 5;
    int v = (i < N_NODES) ? g_cnt[i] : 0;
    int s = v;
    #pragma unroll
    for (int o = 1; o < 32; o <<= 1) { int t = __shfl_up_sync(~0u, s, o); if (lane >= o) s += t; }
    if (lane == 31) wsum[wid] = s;
    __syncthreads();
    if (wid == 0) {
        int ws = (lane < SCAN_B / 32) ? wsum[lane] : 0;
        #pragma unroll
        for (int o = 1; o < SCAN_B / 32; o <<= 1) { int t = __shfl_up_sync(~0u, ws, o); if (lane >= o) ws += t; }
        if (lane < SCAN_B / 32) wsum[lane] = ws;
    }
    __syncthreads();
    int base = (wid > 0) ? wsum[wid - 1] : 0;
    if (i < N_NODES) g_off[i] = base + s - v;
    if (threadIdx.x == SCAN_B - 1) g_bsum[blockIdx.x] = base + s;
}

__global__ __launch_bounds__(256) void k_scan2() {
    __shared__ int wsum[8];
    int lane = threadIdx.x & 31, wid = threadIdx.x >> 5;
    int v = (threadIdx.x < NBLK) ? g_bsum[threadIdx.x] : 0;
    int s = v;
    #pragma unroll
    for (int o = 1; o < 32; o <<= 1) { int t = __shfl_up_sync(~0u, s, o); if (lane >= o) s += t; }
    if (lane == 31) wsum[wid] = s;
    __syncthreads();
    if (wid == 0) {
        int ws = (lane < 8) ? wsum[lane] : 0;
        #pragma unroll
        for (int o = 1; o < 8; o <<= 1) { int t = __shfl_up_sync(~0u, ws, o); if (lane >= o) ws += t; }
        if (lane < 8) wsum[lane] = ws;
    }
    __syncthreads();
    int base = (wid > 0) ? wsum[wid - 1] : 0;
    if (threadIdx.x < NBLK) g_bsum[threadIdx.x] = base + s - v;
}

__global__ __launch_bounds__(SCAN_B) void k_scan3() {
    int i = blockIdx.x * SCAN_B + threadIdx.x;
    if (i < N_NODES) g_off[i] += g_bsum[blockIdx.x];
}

__global__ __launch_bounds__(256) void k_bin(const int* __restrict__ row, const int* __restrict__ col) {
    int e = blockIdx.x * blockDim.x + threadIdx.x;
    if (e >= E_EDGES) return;
    int r = row[e];
    int pos = g_off[r] + atomicAdd(&g_cur[r], 1);
    g_ecol[pos] = col[e];
}

// ---- pre-transpose + fp16-split W into g_wh[mat][hi/lo][n][k] ----
__global__ __launch_bounds__(256) void k_wsplit(const float* __restrict__ W_fc,
                                                const float* __restrict__ W_rate,
                                                const float* __restrict__ W_rob) {
    int t = blockIdx.x * blockDim.x + threadIdx.x;   // 3*128*32 = 12288
    if (t >= 3 * 128 * 32) return;
    int mat = t >> 12;
    int n = (t & 4095) >> 5;
    int k0 = (t & 31) << 2;
    const float* W = (mat == 0) ? W_fc : ((mat == 1) ? W_rate : W_rob);
    __half hi[4], lo[4];
    #pragma unroll
    for (int i = 0; i < 4; i++) {
        float v = W[(size_t)(k0 + i) * D + n];
        __half h = __float2half_rn(v);
        hi[i] = h;
        lo[i] = __float2half_rn(v - __half2float(h));
    }
    size_t oh = ((size_t)(mat * 2 + 0) << 14) + (n << 7) + k0;
    size_t ol = ((size_t)(mat * 2 + 1) << 14) + (n << 7) + k0;
    *(uint2*)(g_wh + oh) = *(uint2*)hi;
    *(uint2*)(g_wh + ol) = *(uint2*)lo;
}

// ============================ mma.sync fused 3x GEMM ============================
// smem: x_hi [0,32K)  x_lo [32K,64K)  Wbuf0 [64K,128K)  Wbuf1 [128K,192K)
// each Wbuf: hi [0,32K) + lo [32K,64K); all fp16 [row][k] rows of 256B,
// 16B-unit swizzle: unit u -> u ^ (row & 7).
#define SM_XHI   0
#define SM_XLO   32768
#define SM_WB    65536
#define SM_TOTAL (65536 + 2 * 65536)   // 196608

__global__ __launch_bounds__(256, 1) void k_mm(const float* __restrict__ x,
                                               const float* __restrict__ b_fc,
                                               const float* __restrict__ b_rob) {
    extern __shared__ char smem[];
    const uint32_t sbase = smem_u32(smem);
    const int tid = threadIdx.x;
    const int wid = tid >> 5;
    const int lane = tid & 31;
    const int m0 = blockIdx.x * TILE_M;
    const int warpM = wid & 3;     // rows 32*warpM .. +32
    const int warpN = wid >> 2;    // cols 64*warpN .. +64

    // ---- stage x tile as fp16 hi/lo ----
    #pragma unroll
    for (int r = 0; r < 16; r++) {
        int idx = (r << 8) + tid;           // 0..4095
        int m = idx >> 5;
        int kq = idx & 31;                  // float4 index; k0 = kq*4
        float4 v = make_float4(0.f, 0.f, 0.f, 0.f);
        if (m0 + m < N_NODES) v = *(const float4*)(x + (size_t)(m0 + m) * D + (kq << 2));
        __half hx = __float2half_rn(v.x), hy = __float2half_rn(v.y);
        __half hz = __float2half_rn(v.z), hw = __float2half_rn(v.w);
        __half lx = __float2half_rn(v.x - __half2float(hx));
        __half ly = __float2half_rn(v.y - __half2float(hy));
        __half lz = __float2half_rn(v.z - __half2float(hz));
        __half lw = __float2half_rn(v.w - __half2float(hw));
        uint2 hp, lp;
        hp.x = __half_as_ushort(hx) | ((uint32_t)__half_as_ushort(hy) << 16);
        hp.y = __half_as_ushort(hz) | ((uint32_t)__half_as_ushort(hw) << 16);
        lp.x = __half_as_ushort(lx) | ((uint32_t)__half_as_ushort(ly) << 16);
        lp.y = __half_as_ushort(lz) | ((uint32_t)__half_as_ushort(lw) << 16);
        int u = kq >> 1;                    // 16B unit (k0/8)
        int off8 = (kq & 1) << 3;
        uint32_t so = (uint32_t)(m * 256 + (((u ^ (m & 7))) << 4) + off8);
        *(uint2*)(smem + SM_XHI + so) = hp;
        *(uint2*)(smem + SM_XLO + so) = lp;
    }

    // ---- prefetch W[0] into buf0 ----
    {
        const char* wsrc = (const char*)g_wh;   // mat 0 at offset 0
        #pragma unroll
        for (int r = 0; r < 16; r++) {
            int idx = (r << 8) + tid;           // 0..4095 (16B units)
            int h = idx >> 11;                  // hi/lo
            int rem = idx & 2047;
            int n = rem >> 4;
            int u = rem & 15;
            uint32_t dst = sbase + SM_WB + (h << 15) + (uint32_t)(n * 256 + ((u ^ (n & 7)) << 4));
            cp_async16(dst, wsrc + ((size_t)h << 15) + (size_t)n * 256 + (u << 4));
        }
        cp_commit();
    }
    cp_wait0();
    __syncthreads();

    // per-thread ldmatrix address components
    const int rowA_off = (lane & 7) + (((lane >> 3) & 1) << 3);
    const int dA = lane >> 4;
    const int nB_off = (lane & 7) + (((lane >> 4) & 1) << 3);
    const int dB = (lane >> 3) & 1;

    int rowA[2], s7A[2];
    #pragma unroll
    for (int mt = 0; mt < 2; mt++) {
        int rr = warpM * 32 + mt * 16 + rowA_off;
        rowA[mt] = rr * 256; s7A[mt] = rr & 7;
    }
    int rowB[4], s7B[4];
    #pragma unroll
    for (int nt2 = 0; nt2 < 4; nt2++) {
        int nn = warpN * 64 + nt2 * 16 + nB_off;
        rowB[nt2] = nn * 256; s7B[nt2] = nn & 7;
    }

    const int g4 = lane >> 2;      // C-frag row within tile
    const int t4 = lane & 3;       // C-frag col pair

    for (int mat = 0; mat < 3; mat++) {
        const int cur = mat & 1;
        // prefetch next W
        if (mat < 2) {
            const char* wsrc = (const char*)g_wh + ((size_t)(mat + 1) << 16);  // *2 mats *32KB
            #pragma unroll
            for (int r = 0; r < 16; r++) {
                int idx = (r << 8) + tid;
                int h = idx >> 11;
                int rem = idx & 2047;
                int n = rem >> 4;
                int u = rem & 15;
                uint32_t dst = sbase + SM_WB + (((mat + 1) & 1) << 16)
                             + (h << 15) + (uint32_t)(n * 256 + ((u ^ (n & 7)) << 4));
                cp_async16(dst, wsrc + ((size_t)h << 15) + (size_t)n * 256 + (u << 4));
            }
            cp_commit();
        }

        float acc[2][8][4];
        #pragma unroll
        for (int mt = 0; mt < 2; mt++)
            #pragma unroll
            for (int nt = 0; nt < 8; nt++)
                #pragma unroll
                for (int i = 0; i < 4; i++) acc[mt][nt][i] = 0.f;

        const uint32_t wb = sbase + SM_WB + (cur << 16);
        #pragma unroll 1
        for (int term = 0; term < 3; term++) {
            const uint32_t abase = sbase + ((term == 2) ? SM_XLO : SM_XHI);
            const uint32_t bbase = wb + ((term == 1) ? 32768u : 0u);
            #pragma unroll 1
            for (int ks = 0; ks < 8; ks++) {
                uint32_t a[2][4];
                #pragma unroll
                for (int mt = 0; mt < 2; mt++) {
                    int u = 2 * ks + dA;
                    ldmatrix4(a[mt], abase + rowA[mt] + ((u ^ s7A[mt]) << 4));
                }
                uint32_t b[4][4];
                #pragma unroll
                for (int nt2 = 0; nt2 < 4; nt2++) {
                    int u = 2 * ks + dB;
                    ldmatrix4(b[nt2], bbase + rowB[nt2] + ((u ^ s7B[nt2]) << 4));
                }
                #pragma unroll
                for (int mt = 0; mt < 2; mt++)
                    #pragma unroll
                    for (int nt = 0; nt < 8; nt++)
                        mma16816(acc[mt][nt], a[mt], b[nt >> 1][(nt & 1) << 1], b[nt >> 1][((nt & 1) << 1) + 1]);
            }
        }

        // ---- epilogue for this mat ----
        {
            float* outp = (mat == 0) ? g_h : ((mat == 1) ? g_rate : g_gamma);
            const float* bias = (mat == 0) ? b_fc : b_rob;
            #pragma unroll
            for (int mt = 0; mt < 2; mt++) {
                int r0 = m0 + warpM * 32 + mt * 16 + g4;
                int r1 = r0 + 8;
                #pragma unroll
                for (int nt = 0; nt < 8; nt++) {
                    int col = warpN * 64 + nt * 8 + t4 * 2;
                    float v0 = acc[mt][nt][0], v1 = acc[mt][nt][1];
                    float v2 = acc[mt][nt][2], v3 = acc[mt][nt][3];
                    if (mat == 1) {
                        v0 = ((v0 > 20.f) ? v0 : log1pf(__expf(v0))) + EPSV;
                        v1 = ((v1 > 20.f) ? v1 : log1pf(__expf(v1))) + EPSV;
                        v2 = ((v2 > 20.f) ? v2 : log1pf(__expf(v2))) + EPSV;
                        v3 = ((v3 > 20.f) ? v3 : log1pf(__expf(v3))) + EPSV;
                    } else {
                        float b0 = bias[col], b1 = bias[col + 1];
                        v0 += b0; v1 += b1; v2 += b0; v3 += b1;
                    }
                    if (r0 < N_NODES) *(float2*)(outp + (size_t)r0 * D + col) = make_float2(v0, v1);
                    if (r1 < N_NODES) *(float2*)(outp + (size_t)r1 * D + col) = make_float2(v2, v3);
                }
            }
        }

        if (mat < 2) { cp_wait0(); __syncthreads(); }
    }
}

// ---------------- fused gather + combine + LayerNorm (one warp per node) ----
__global__ __launch_bounds__(256) void k_final(const int* __restrict__ degree,
                                               const float* __restrict__ ln_g,
                                               const float* __restrict__ ln_b,
                                               float* __restrict__ out)
{
    int w = (blockIdx.x * blockDim.x + threadIdx.x) >> 5;
    int lane = threadIdx.x & 31;
    if (w >= N_NODES) return;
    size_t base = (size_t)w * D;

    int start = g_off[w];
    int cnt = g_cnt[w];

    float4 acc = make_float4(0.f, 0.f, 0.f, 0.f);
    int j = 0;
    for (; j + 4 <= cnt; j += 4) {
        int c0 = g_ecol[start + j + 0];
        int c1 = g_ecol[start + j + 1];
        int c2 = g_ecol[start + j + 2];
        int c3 = g_ecol[start + j + 3];
        float4 v0 = ((const float4*)(g_h + (size_t)c0 * D))[lane];
        float4 v1 = ((const float4*)(g_h + (size_t)c1 * D))[lane];
        float4 v2 = ((const float4*)(g_h + (size_t)c2 * D))[lane];
        float4 v3 = ((const float4*)(g_h + (size_t)c3 * D))[lane];
        acc.x += (v0.x + v1.x) + (v2.x + v3.x);
        acc.y += (v0.y + v1.y) + (v2.y + v3.y);
        acc.z += (v0.z + v1.z) + (v2.z + v3.z);
        acc.w += (v0.w + v1.w) + (v2.w + v3.w);
    }
    for (; j < cnt; j++) {
        int c = g_ecol[start + j];
        float4 v = ((const float4*)(g_h + (size_t)c * D))[lane];
        acc.x += v.x; acc.y += v.y; acc.z += v.z; acc.w += v.w;
    }

    float4 h4 = ((const float4*)(g_h + base))[lane];
    float4 r4 = ((const float4*)(g_rate + base))[lane];
    float4 g4 = ((const float4*)(g_gamma + base))[lane];
    float fc = (float)cnt;
    float deg = (float)degree[w];

    float y[4];
    {
        const float* hp = (const float*)&h4;
        const float* ap = (const float*)&acc;
        const float* rp = (const float*)&r4;
        const float* gp = (const float*)&g4;
        #pragma unroll
        for (int i = 0; i < 4; i++) {
            float agg_full = ap[i] + fc * hp[i];
            y[i] = (rp[i] * agg_full + gp[i]) / (1.0f + EPSV + rp[i] * deg);
        }
    }

    float s = y[0] + y[1] + y[2] + y[3];
    float s2 = y[0]*y[0] + y[1]*y[1] + y[2]*y[2] + y[3]*y[3];
    #pragma unroll
    for (int off = 16; off > 0; off >>= 1) {
        s  += __shfl_xor_sync(0xffffffffu, s,  off);
        s2 += __shfl_xor_sync(0xffffffffu, s2, off);
    }
    float mean = s * (1.0f / D);
    float var = s2 * (1.0f / D) - mean * mean;
    float rstd = rsqrtf(var + LN_EPSV);

    float4 lg = ((const float4*)ln_g)[lane];
    float4 lb = ((const float4*)ln_b)[lane];
    float4 o;
    o.x = (y[0] - mean) * rstd * lg.x + lb.x;
    o.y = (y[1] - mean) * rstd * lg.y + lb.y;
    o.z = (y[2] - mean) * rstd * lg.z + lb.z;
    o.w = (y[3] - mean) * rstd * lg.w + lb.w;
    ((float4*)(out + base))[lane] = o;
}

// ---------------- launch ----------------
extern "C" void kernel_launch(void* const* d_in, const int* in_sizes, int n_in,
                              void* d_out, int out_size) {
    const float* x      = (const float*)d_in[0];
    const int*   ei     = (const int*)  d_in[1];
    const int*   degree = (const int*)  d_in[2];
    const float* W_fc   = (const float*)d_in[3];
    const float* b_fc   = (const float*)d_in[4];
    const float* W_rate = (const float*)d_in[5];
    const float* W_rob  = (const float*)d_in[6];
    const float* b_rob  = (const float*)d_in[7];
    const float* ln_g   = (const float*)d_in[8];
    const float* ln_b   = (const float*)d_in[9];
    float* out = (float*)d_out;

    const int* row = ei;             // edge_index[0]
    const int* col = ei + E_EDGES;   // edge_index[1]

    cudaFuncSetAttribute(k_mm, cudaFuncAttributeMaxDynamicSharedMemorySize, SM_TOTAL);

    k_zero<<<(N_NODES + 255) / 256, 256>>>();
    k_count<<<(E_EDGES + 255) / 256, 256>>>(row);
    k_wsplit<<<(3 * 128 * 32 + 255) / 256, 256>>>(W_fc, W_rate, W_rob);
    k_scan1<<<NBLK, SCAN_B>>>();
    k_scan2<<<1, 256>>>();
    k_scan3<<<NBLK, SCAN_B>>>();
    k_bin<<<(E_EDGES + 255) / 256, 256>>>(row, col);
    k_mm<<<MM_CTAS, 256, SM_TOTAL>>>(x, b_fc, b_rob);
    k_final<<<(int)(((size_t)N_NODES * 32 + 255) / 256), 256>>>(degree, ln_g, ln_b, out);
}

// round 6
// speedup vs baseline: 1.6428x; 1.1054x over previous
#include <cuda_runtime.h>
#include <cuda_fp16.h>
#include <math.h>
#include <cstdint>

#define N_NODES 100000
#define E_EDGES 800000
#define D 128
#define EPSV 1e-4f
#define LN_EPSV 1e-5f

#define SCAN_B 512
#define NBLK ((N_NODES + SCAN_B - 1) / SCAN_B)   // 196

#define TILE_M 256
#define MM_CTAS ((N_NODES + TILE_M - 1) / TILE_M)  // 391
#define MM_THREADS 512

// ---- scratch (device globals; no allocation allowed) ----
__device__ float  g_h[(size_t)N_NODES * D];
__device__ float  g_rate[(size_t)N_NODES * D];
__device__ float  g_gamma[(size_t)N_NODES * D];
__device__ int    g_cnt[N_NODES];
__device__ int    g_cur[N_NODES];
__device__ int    g_off[N_NODES];
__device__ int    g_bsum[NBLK];
__device__ int    g_ecol[E_EDGES];
// fp16-split, transposed weights: [mat(3)][hi/lo(2)][n(128)][k(128)] halves
__device__ __half g_wh[3 * 2 * 128 * 128];

// ============================ helpers ============================
__device__ __forceinline__ uint32_t smem_u32(const void* p) {
    uint32_t a;
    asm("{ .reg .u64 t; cvta.to.shared.u64 t, %1; cvt.u32.u64 %0, t; }" : "=r"(a) : "l"(p));
    return a;
}

__device__ __forceinline__ void ldmatrix4(uint32_t* r, uint32_t addr) {
    asm volatile("ldmatrix.sync.aligned.m8n8.x4.shared.b16 {%0,%1,%2,%3}, [%4];"
                 : "=r"(r[0]), "=r"(r[1]), "=r"(r[2]), "=r"(r[3]) : "r"(addr));
}

__device__ __forceinline__ void mma16816(float* c, const uint32_t* a, uint32_t b0, uint32_t b1) {
    asm volatile("mma.sync.aligned.m16n8k16.row.col.f32.f16.f16.f32 "
                 "{%0,%1,%2,%3}, {%4,%5,%6,%7}, {%8,%9}, {%0,%1,%2,%3};"
                 : "+f"(c[0]), "+f"(c[1]), "+f"(c[2]), "+f"(c[3])
                 : "r"(a[0]), "r"(a[1]), "r"(a[2]), "r"(a[3]), "r"(b0), "r"(b1));
}

__device__ __forceinline__ void cp_async16(uint32_t saddr, const void* gaddr) {
    asm volatile("cp.async.cg.shared.global [%0], [%1], 16;" :: "r"(saddr), "l"(gaddr));
}
__device__ __forceinline__ void cp_commit() { asm volatile("cp.async.commit_group;"); }
__device__ __forceinline__ void cp_wait0()  { asm volatile("cp.async.wait_group 0;" ::: "memory"); }

// ============================ small kernels ============================
__global__ void k_zero() {
    int i = blockIdx.x * blockDim.x + threadIdx.x;
    if (i < N_NODES) g_cnt[i] = 0;
}

__global__ void k_count(const int* __restrict__ row) {
    int e = blockIdx.x * blockDim.x + threadIdx.x;
    if (e < E_EDGES) atomicAdd(&g_cnt[row[e]], 1);
}

__global__ __launch_bounds__(SCAN_B) void k_scan1() {
    __shared__ int wsum[SCAN_B / 32];
    int i = blockIdx.x * SCAN_B + threadIdx.x;
    int lane = threadIdx.x & 31, wid = threadIdx.x >> 5;
    int v = (i < N_NODES) ? g_cnt[i] : 0;
    if (i < N_NODES) g_cur[i] = 0;
    int s = v;
    #pragma unroll
    for (int o = 1; o < 32; o <<= 1) { int t = __shfl_up_sync(~0u, s, o); if (lane >= o) s += t; }
    if (lane == 31) wsum[wid] = s;
    __syncthreads();
    if (wid == 0) {
        int ws = (lane < SCAN_B / 32) ? wsum[lane] : 0;
        #pragma unroll
        for (int o = 1; o < SCAN_B / 32; o <<= 1) { int t = __shfl_up_sync(~0u, ws, o); if (lane >= o) ws += t; }
        if (lane < SCAN_B / 32) wsum[lane] = ws;
    }
    __syncthreads();
    int base = (wid > 0) ? wsum[wid - 1] : 0;
    if (i < N_NODES) g_off[i] = base + s - v;
    if (threadIdx.x == SCAN_B - 1) g_bsum[blockIdx.x] = base + s;
}

__global__ __launch_bounds__(256) void k_scan2() {
    __shared__ int wsum[8];
    int lane = threadIdx.x & 31, wid = threadIdx.x >> 5;
    int v = (threadIdx.x < NBLK) ? g_bsum[threadIdx.x] : 0;
    int s = v;
    #pragma unroll
    for (int o = 1; o < 32; o <<= 1) { int t = __shfl_up_sync(~0u, s, o); if (lane >= o) s += t; }
    if (lane == 31) wsum[wid] = s;
    __syncthreads();
    if (wid == 0) {
        int ws = (lane < 8) ? wsum[lane] : 0;
        #pragma unroll
        for (int o = 1; o < 8; o <<= 1) { int t = __shfl_up_sync(~0u, ws, o); if (lane >= o) ws += t; }
        if (lane < 8) wsum[lane] = ws;
    }
    __syncthreads();
    int base = (wid > 0) ? wsum[wid - 1] : 0;
    if (threadIdx.x < NBLK) g_bsum[threadIdx.x] = base + s - v;
}

// bin: pos = local_off + block_base + rank (scan3 folded in)
__global__ __launch_bounds__(256) void k_bin(const int* __restrict__ row, const int* __restrict__ col) {
    int e = blockIdx.x * blockDim.x + threadIdx.x;
    if (e >= E_EDGES) return;
    int r = row[e];
    int pos = g_off[r] + g_bsum[r >> 9] + atomicAdd(&g_cur[r], 1);
    g_ecol[pos] = col[e];
}

// ---- pre-transpose + fp16-split W into g_wh[mat][hi/lo][n][k] ----
__global__ __launch_bounds__(256) void k_wsplit(const float* __restrict__ W_fc,
                                                const float* __restrict__ W_rate,
                                                const float* __restrict__ W_rob) {
    int t = blockIdx.x * blockDim.x + threadIdx.x;   // 3*128*32 = 12288
    if (t >= 3 * 128 * 32) return;
    int mat = t >> 12;
    int n = (t & 4095) >> 5;
    int k0 = (t & 31) << 2;
    const float* W = (mat == 0) ? W_fc : ((mat == 1) ? W_rate : W_rob);
    __half hi[4], lo[4];
    #pragma unroll
    for (int i = 0; i < 4; i++) {
        float v = W[(size_t)(k0 + i) * D + n];
        __half h = __float2half_rn(v);
        hi[i] = h;
        lo[i] = __float2half_rn(v - __half2float(h));
    }
    size_t oh = ((size_t)(mat * 2 + 0) << 14) + (n << 7) + k0;
    size_t ol = ((size_t)(mat * 2 + 1) << 14) + (n << 7) + k0;
    *(uint2*)(g_wh + oh) = *(uint2*)hi;
    *(uint2*)(g_wh + ol) = *(uint2*)lo;
}

// ============================ mma.sync fused 3x GEMM ============================
// TILE_M=256, 512 threads (16 warps: 8 M-groups x 2 N-groups).
// smem: x_hi [0,64K)  x_lo [64K,128K)  Wbuf [128K,192K) single-buffered
// fp16 [row][k] rows of 256B, 16B-unit swizzle: unit u -> u ^ (row & 7).
#define SM_XHI   0
#define SM_XLO   65536
#define SM_WB    131072
#define SM_TOTAL (131072 + 65536)   // 196608

__global__ __launch_bounds__(MM_THREADS, 1) void k_mm(const float* __restrict__ x,
                                                      const float* __restrict__ b_fc,
                                                      const float* __restrict__ b_rob) {
    extern __shared__ char smem[];
    const uint32_t sbase = smem_u32(smem);
    const int tid = threadIdx.x;
    const int wid = tid >> 5;
    const int lane = tid & 31;
    const int m0 = blockIdx.x * TILE_M;
    const int warpM = wid & 7;     // rows 32*warpM .. +32
    const int warpN = wid >> 3;    // cols 64*warpN .. +64

    // ---- stage x tile as fp16 hi/lo (256 rows x 128 k) ----
    #pragma unroll
    for (int r = 0; r < 16; r++) {
        int idx = (r << 9) + tid;           // 0..8191
        int m = idx >> 5;
        int kq = idx & 31;                  // float4 index; k0 = kq*4
        float4 v = make_float4(0.f, 0.f, 0.f, 0.f);
        if (m0 + m < N_NODES) v = *(const float4*)(x + (size_t)(m0 + m) * D + (kq << 2));
        __half hx = __float2half_rn(v.x), hy = __float2half_rn(v.y);
        __half hz = __float2half_rn(v.z), hw = __float2half_rn(v.w);
        __half lx = __float2half_rn(v.x - __half2float(hx));
        __half ly = __float2half_rn(v.y - __half2float(hy));
        __half lz = __float2half_rn(v.z - __half2float(hz));
        __half lw = __float2half_rn(v.w - __half2float(hw));
        uint2 hp, lp;
        hp.x = __half_as_ushort(hx) | ((uint32_t)__half_as_ushort(hy) << 16);
        hp.y = __half_as_ushort(hz) | ((uint32_t)__half_as_ushort(hw) << 16);
        lp.x = __half_as_ushort(lx) | ((uint32_t)__half_as_ushort(ly) << 16);
        lp.y = __half_as_ushort(lz) | ((uint32_t)__half_as_ushort(lw) << 16);
        int u = kq >> 1;                    // 16B unit
        int off8 = (kq & 1) << 3;
        uint32_t so = (uint32_t)(m * 256 + ((u ^ (m & 7)) << 4) + off8);
        *(uint2*)(smem + SM_XHI + so) = hp;
        *(uint2*)(smem + SM_XLO + so) = lp;
    }

    // ---- prefetch W[0] (hi+lo, 64KB = 4096 16B units, 8 per thread) ----
    {
        const char* wsrc = (const char*)g_wh;
        #pragma unroll
        for (int r = 0; r < 8; r++) {
            int idx = (r << 9) + tid;           // 0..4095
            int h = idx >> 11;
            int rem = idx & 2047;
            int n = rem >> 4;
            int u = rem & 15;
            uint32_t dst = sbase + SM_WB + (h << 15) + (uint32_t)(n * 256 + ((u ^ (n & 7)) << 4));
            cp_async16(dst, wsrc + ((size_t)h << 15) + (size_t)n * 256 + (u << 4));
        }
        cp_commit();
    }
    cp_wait0();
    __syncthreads();

    // per-thread ldmatrix address components
    const int rowA_off = (lane & 7) + (((lane >> 3) & 1) << 3);
    const int dA = lane >> 4;
    const int nB_off = (lane & 7) + (((lane >> 4) & 1) << 3);
    const int dB = (lane >> 3) & 1;

    int rowA[2], s7A[2];
    #pragma unroll
    for (int mt = 0; mt < 2; mt++) {
        int rr = warpM * 32 + mt * 16 + rowA_off;
        rowA[mt] = rr * 256; s7A[mt] = rr & 7;
    }
    int rowB[4], s7B[4];
    #pragma unroll
    for (int nt2 = 0; nt2 < 4; nt2++) {
        int nn = warpN * 64 + nt2 * 16 + nB_off;
        rowB[nt2] = nn * 256; s7B[nt2] = nn & 7;
    }

    const int g4 = lane >> 2;      // C-frag row within tile
    const int t4 = lane & 3;       // C-frag col pair

    for (int mat = 0; mat < 3; mat++) {
        float acc[2][8][4];
        #pragma unroll
        for (int mt = 0; mt < 2; mt++)
            #pragma unroll
            for (int nt = 0; nt < 8; nt++)
                #pragma unroll
                for (int i = 0; i < 4; i++) acc[mt][nt][i] = 0.f;

        #pragma unroll 1
        for (int term = 0; term < 3; term++) {
            const uint32_t abase = sbase + ((term == 2) ? SM_XLO : SM_XHI);
            const uint32_t bbase = sbase + SM_WB + ((term == 1) ? 32768u : 0u);
            #pragma unroll 1
            for (int ks = 0; ks < 8; ks++) {
                uint32_t a[2][4];
                #pragma unroll
                for (int mt = 0; mt < 2; mt++) {
                    int u = 2 * ks + dA;
                    ldmatrix4(a[mt], abase + rowA[mt] + ((u ^ s7A[mt]) << 4));
                }
                uint32_t b[4][4];
                #pragma unroll
                for (int nt2 = 0; nt2 < 4; nt2++) {
                    int u = 2 * ks + dB;
                    ldmatrix4(b[nt2], bbase + rowB[nt2] + ((u ^ s7B[nt2]) << 4));
                }
                #pragma unroll
                for (int mt = 0; mt < 2; mt++)
                    #pragma unroll
                    for (int nt = 0; nt < 8; nt++)
                        mma16816(acc[mt][nt], a[mt], b[nt >> 1][(nt & 1) << 1], b[nt >> 1][((nt & 1) << 1) + 1]);
            }
        }

        // all warps done reading W[mat]; overlap next-W load with epilogue
        if (mat < 2) {
            __syncthreads();
            const char* wsrc = (const char*)g_wh + ((size_t)(mat + 1) << 16);
            #pragma unroll
            for (int r = 0; r < 8; r++) {
                int idx = (r << 9) + tid;
                int h = idx >> 11;
                int rem = idx & 2047;
                int n = rem >> 4;
                int u = rem & 15;
                uint32_t dst = sbase + SM_WB + (h << 15) + (uint32_t)(n * 256 + ((u ^ (n & 7)) << 4));
                cp_async16(dst, wsrc + ((size_t)h << 15) + (size_t)n * 256 + (u << 4));
            }
            cp_commit();
        }

        // ---- epilogue for this mat ----
        {
            float* outp = (mat == 0) ? g_h : ((mat == 1) ? g_rate : g_gamma);
            const float* bias = (mat == 0) ? b_fc : b_rob;
            #pragma unroll
            for (int mt = 0; mt < 2; mt++) {
                int r0 = m0 + warpM * 32 + mt * 16 + g4;
                int r1 = r0 + 8;
                #pragma unroll
                for (int nt = 0; nt < 8; nt++) {
                    int col = warpN * 64 + nt * 8 + t4 * 2;
                    float v0 = acc[mt][nt][0], v1 = acc[mt][nt][1];
                    float v2 = acc[mt][nt][2], v3 = acc[mt][nt][3];
                    if (mat == 1) {
                        v0 = ((v0 > 20.f) ? v0 : log1pf(__expf(v0))) + EPSV;
                        v1 = ((v1 > 20.f) ? v1 : log1pf(__expf(v1))) + EPSV;
                        v2 = ((v2 > 20.f) ? v2 : log1pf(__expf(v2))) + EPSV;
                        v3 = ((v3 > 20.f) ? v3 : log1pf(__expf(v3))) + EPSV;
                    } else {
                        float b0 = bias[col], b1 = bias[col + 1];
                        v0 += b0; v1 += b1; v2 += b0; v3 += b1;
                    }
                    if (r0 < N_NODES) *(float2*)(outp + (size_t)r0 * D + col) = make_float2(v0, v1);
                    if (r1 < N_NODES) *(float2*)(outp + (size_t)r1 * D + col) = make_float2(v2, v3);
                }
            }
        }

        if (mat < 2) { cp_wait0(); __syncthreads(); }
    }
}

// ---------------- fused gather + combine + LayerNorm (one warp per node) ----
__global__ __launch_bounds__(256) void k_final(const int* __restrict__ degree,
                                               const float* __restrict__ ln_g,
                                               const float* __restrict__ ln_b,
                                               float* __restrict__ out)
{
    int w = (blockIdx.x * blockDim.x + threadIdx.x) >> 5;
    int lane = threadIdx.x & 31;
    if (w >= N_NODES) return;
    size_t base = (size_t)w * D;

    int start = g_off[w] + g_bsum[w >> 9];
    int cnt = g_cnt[w];

    float4 acc = make_float4(0.f, 0.f, 0.f, 0.f);
    int j = 0;
    for (; j + 4 <= cnt; j += 4) {
        int c0 = g_ecol[start + j + 0];
        int c1 = g_ecol[start + j + 1];
        int c2 = g_ecol[start + j + 2];
        int c3 = g_ecol[start + j + 3];
        float4 v0 = __ldg(((const float4*)(g_h + (size_t)c0 * D)) + lane);
        float4 v1 = __ldg(((const float4*)(g_h + (size_t)c1 * D)) + lane);
        float4 v2 = __ldg(((const float4*)(g_h + (size_t)c2 * D)) + lane);
        float4 v3 = __ldg(((const float4*)(g_h + (size_t)c3 * D)) + lane);
        acc.x += (v0.x + v1.x) + (v2.x + v3.x);
        acc.y += (v0.y + v1.y) + (v2.y + v3.y);
        acc.z += (v0.z + v1.z) + (v2.z + v3.z);
        acc.w += (v0.w + v1.w) + (v2.w + v3.w);
    }
    for (; j < cnt; j++) {
        int c = g_ecol[start + j];
        float4 v = __ldg(((const float4*)(g_h + (size_t)c * D)) + lane);
        acc.x += v.x; acc.y += v.y; acc.z += v.z; acc.w += v.w;
    }

    float4 h4 = ((const float4*)(g_h + base))[lane];
    float4 r4 = ((const float4*)(g_rate + base))[lane];
    float4 g4 = ((const float4*)(g_gamma + base))[lane];
    float fc = (float)cnt;
    float deg = (float)degree[w];

    float y[4];
    {
        const float* hp = (const float*)&h4;
        const float* ap = (const float*)&acc;
        const float* rp = (const float*)&r4;
        const float* gp = (const float*)&g4;
        #pragma unroll
        for (int i = 0; i < 4; i++) {
            float agg_full = ap[i] + fc * hp[i];
            y[i] = (rp[i] * agg_full + gp[i]) / (1.0f + EPSV + rp[i] * deg);
        }
    }

    float s = y[0] + y[1] + y[2] + y[3];
    float s2 = y[0]*y[0] + y[1]*y[1] + y[2]*y[2] + y[3]*y[3];
    #pragma unroll
    for (int off = 16; off > 0; off >>= 1) {
        s  += __shfl_xor_sync(0xffffffffu, s,  off);
        s2 += __shfl_xor_sync(0xffffffffu, s2, off);
    }
    float mean = s * (1.0f / D);
    float var = s2 * (1.0f / D) - mean * mean;
    float rstd = rsqrtf(var + LN_EPSV);

    float4 lg = ((const float4*)ln_g)[lane];
    float4 lb = ((const float4*)ln_b)[lane];
    float4 o;
    o.x = (y[0] - mean) * rstd * lg.x + lb.x;
    o.y = (y[1] - mean) * rstd * lg.y + lb.y;
    o.z = (y[2] - mean) * rstd * lg.z + lb.z;
    o.w = (y[3] - mean) * rstd * lg.w + lb.w;
    ((float4*)(out + base))[lane] = o;
}

// ---------------- launch ----------------
extern "C" void kernel_launch(void* const* d_in, const int* in_sizes, int n_in,
                              void* d_out, int out_size) {
    const float* x      = (const float*)d_in[0];
    const int*   ei     = (const int*)  d_in[1];
    const int*   degree = (const int*)  d_in[2];
    const float* W_fc   = (const float*)d_in[3];
    const float* b_fc   = (const float*)d_in[4];
    const float* W_rate = (const float*)d_in[5];
    const float* W_rob  = (const float*)d_in[6];
    const float* b_rob  = (const float*)d_in[7];
    const float* ln_g   = (const float*)d_in[8];
    const float* ln_b   = (const float*)d_in[9];
    float* out = (float*)d_out;

    const int* row = ei;             // edge_index[0]
    const int* col = ei + E_EDGES;   // edge_index[1]

    cudaFuncSetAttribute(k_mm, cudaFuncAttributeMaxDynamicSharedMemorySize, SM_TOTAL);

    k_zero<<<(N_NODES + 255) / 256, 256>>>();
    k_count<<<(E_EDGES + 255) / 256, 256>>>(row);
    k_wsplit<<<(3 * 128 * 32 + 255) / 256, 256>>>(W_fc, W_rate, W_rob);
    k_scan1<<<NBLK, SCAN_B>>>();
    k_scan2<<<1, 256>>>();
    k_bin<<<(E_EDGES + 255) / 256, 256>>>(row, col);
    k_mm<<<MM_CTAS, MM_THREADS, SM_TOTAL>>>(x, b_fc, b_rob);
    k_final<<<(int)(((size_t)N_NODES * 32 + 255) / 256), 256>>>(degree, ln_g, ln_b, out);
}